// round 15
// baseline (speedup 1.0000x reference)
#include <cuda_runtime.h>
#include <cuda_fp16.h>
#include <math_constants.h>

#define D      128
#define BGR    512
#define NWARP  8
#define NTHR   256
#define KW     256          // GEMM K (= 2*D)
#define GCOLS  512          // GEMM output cols (4 gates x 128 features, interleaved)
#define STG    3            // per-warp cp.async ring depth
#define GRP    4            // nodes per stage (one per 8-lane group)
#define GRUA_BLKS 64        // embedded h-half GEMM blocks (64x64 tiles)
#define MAXN   204800       // fp16 x-cache capacity (nodes)
#define LOG2E  1.4426950408889634f

// init kernel block-range sizes
#define PREP_BLKS  512      // GCOLS*KW / 256
#define BIAS_BLKS  256      // BGR*D / 256

// ---------------- device scratch (no allocation allowed) ----------------
__device__ float   g_h[BGR * D];            // hidden state (current)
__device__ float   g_Wbig[GCOLS * KW];      // merged weights, col 4f+g
__device__ float   g_bias[GCOLS];           // merged biases [br,bz,bin,bhn] per feature
__device__ int     g_starts[BGR + 1];       // segment boundaries (batch is sorted)
__device__ float   g_acc[BGR * GCOLS];      // h-half GEMM partials (1MB)
__device__ __half  g_xh[(size_t)MAXN * D];  // fp16 copy of x (52MB), built in pass 0

__device__ __forceinline__ float sigf(float v) { return 1.f / (1.f + __expf(-v)); }
__device__ __forceinline__ float ex2f(float v) {
    float r; asm("ex2.approx.f32 %0, %1;" : "=f"(r) : "f"(v)); return r;
}

__device__ __forceinline__ void cp16(void* sdst, const void* gsrc) {
    unsigned s = (unsigned)__cvta_generic_to_shared(sdst);
    asm volatile("cp.async.cg.shared.global [%0], [%1], 16;" :: "r"(s), "l"(gsrc));
}
__device__ __forceinline__ void cp8(void* sdst, const void* gsrc) {
    unsigned s = (unsigned)__cvta_generic_to_shared(sdst);
    asm volatile("cp.async.ca.shared.global [%0], [%1], 8;" :: "r"(s), "l"(gsrc));
}
__device__ __forceinline__ void cp_commit() { asm volatile("cp.async.commit_group;"); }
template<int N> __device__ __forceinline__ void cp_wait() {
    asm volatile("cp.async.wait_group %0;" :: "n"(N));
}

// batch may be delivered as int32 or int64; sniff layout from a mid element.
__device__ __forceinline__ bool batch_is_i64(const void* bp, int N) {
    long long v = ((const long long*)bp)[N >> 2];
    return (v >= 0 && v < BGR);
}
__device__ __forceinline__ int batch_at(const void* bp, int i, bool is64) {
    int v = is64 ? (int)((const long long*)bp)[i] : ((const int*)bp)[i];
    return min(max(v, 0), BGR - 1);
}

// ---------------- fused init: prep (Wbig/bias) + step-1 h + segment starts -------------
__global__ void init_kernel(const void* __restrict__ batch, int N,
                            const float* __restrict__ W_ih, const float* __restrict__ W_hh,
                            const float* __restrict__ b_ih, const float* __restrict__ b_hh) {
    int bx = blockIdx.x;
    int t  = threadIdx.x;

    if (bx < PREP_BLKS) {
        int idx = bx * 256 + t;                 // < GCOLS*KW
        int c = idx >> 8;
        int k = idx & (KW - 1);
        int f = c >> 2, g = c & 3;
        float v;
        if (g == 0)      v = W_ih[(size_t)f * KW + k]         + (k < D ? W_hh[(size_t)f * D + k] : 0.f);
        else if (g == 1) v = W_ih[(size_t)(D + f) * KW + k]   + (k < D ? W_hh[(size_t)(D + f) * D + k] : 0.f);
        else if (g == 2) v = W_ih[(size_t)(2 * D + f) * KW + k];
        else             v = (k < D) ? W_hh[(size_t)(2 * D + f) * D + k] : 0.f;
        g_Wbig[(size_t)c * KW + k] = v;
        if (k == 0) {
            float b;
            if (g == 0)      b = b_ih[f] + b_hh[f];
            else if (g == 1) b = b_ih[D + f] + b_hh[D + f];
            else if (g == 2) b = b_ih[2 * D + f];
            else             b = b_hh[2 * D + f];
            g_bias[c] = b;
        }
    } else if (bx < PREP_BLKS + BIAS_BLKS) {
        int idx = (bx - PREP_BLKS) * 256 + t;   // < BGR*D
        int f = idx & (D - 1);
        float r = sigf(b_ih[f] + b_hh[f]);
        float z = sigf(b_ih[D + f] + b_hh[D + f]);
        float n = tanhf(b_ih[2 * D + f] + r * b_hh[2 * D + f]);
        g_h[idx] = (1.f - z) * n;
    } else {
        int i = (bx - PREP_BLKS - BIAS_BLKS) * 256 + t;
        if (i >= N) return;
        bool is64 = batch_is_i64(batch, N);
        int bi = batch_at(batch, i, is64);
        if (i == 0) {
            for (int b = 0; b <= bi; b++) g_starts[b] = 0;
        } else {
            int bp = batch_at(batch, i - 1, is64);
            for (int b = bp + 1; b <= bi; b++) g_starts[b] = i;
        }
        if (i == N - 1) {
            for (int b = bi + 1; b <= BGR; b++) g_starts[b] = N;
        }
    }
}

// ---------------- gruB: r-half GEMM + gate epilogue (critical path) --------------------
#define GKT 16
__global__ void __launch_bounds__(128) grub_kernel(const float* __restrict__ q_star) {
    __shared__ __align__(16) float As[GKT][32];
    __shared__ __align__(16) float Ws[GKT][64];

    int t  = threadIdx.x;
    int tx = t & 15;
    int ty = t >> 4;           // 0..7 -> 4 rows each
    int r0 = blockIdx.y * 32;
    int c0 = blockIdx.x * 64;

    float acc[4][4];
#pragma unroll
    for (int i = 0; i < 4; i++)
        *(float4*)acc[i] = *(const float4*)(g_acc + (size_t)(r0 + ty * 4 + i) * GCOLS + c0 + tx * 4);

    for (int k0 = 0; k0 < D; k0 += GKT) {
        {   // A tile 32r x 16k from q_star r-half
            int row = t >> 2, k = (t & 3) << 2;
            float4 v = *(const float4*)(q_star + (size_t)(r0 + row) * KW + D + k0 + k);
            As[k][row] = v.x; As[k + 1][row] = v.y; As[k + 2][row] = v.z; As[k + 3][row] = v.w;
        }
        {   // W tile 64c x 16k from Wbig k in [128,256)
            int col = t >> 1, k = (t & 1) << 3;
            const float* wp = g_Wbig + (size_t)(c0 + col) * KW + D + k0 + k;
            float4 v0 = *(const float4*)wp;
            float4 v1 = *(const float4*)(wp + 4);
            Ws[k][col]     = v0.x; Ws[k + 1][col] = v0.y; Ws[k + 2][col] = v0.z; Ws[k + 3][col] = v0.w;
            Ws[k + 4][col] = v1.x; Ws[k + 5][col] = v1.y; Ws[k + 6][col] = v1.z; Ws[k + 7][col] = v1.w;
        }
        __syncthreads();
#pragma unroll
        for (int kk = 0; kk < GKT; kk++) {
            float a[4], w[4];
            *(float4*)a = *(const float4*)&As[kk][ty * 4];
            *(float4*)w = *(const float4*)&Ws[kk][tx * 4];
#pragma unroll
            for (int i = 0; i < 4; i++) {
#pragma unroll
                for (int j = 0; j < 4; j++) acc[i][j] += a[i] * w[j];
            }
        }
        __syncthreads();
    }

    int f = (c0 >> 2) + tx;
    float4 gb = *(const float4*)&g_bias[4 * f];   // [br, bz, bin, bhn]
#pragma unroll
    for (int i = 0; i < 4; i++) {
        int row = r0 + ty * 4 + i;
        float hold = q_star[(size_t)row * KW + f];    // h_old = q half of q_star
        float r = sigf(acc[i][0] + gb.x);
        float z = sigf(acc[i][1] + gb.y);
        float n = tanhf(acc[i][2] + gb.z + r * (acc[i][3] + gb.w));
        g_h[(size_t)row * D + f] = (1.f - z) * n + z * hold;
    }
}

// ---------------- gruA block body (shared by both attn kernels) ------------------------
__device__ __forceinline__ void gruA_block(int gb, float* smem, int t) {
    int r0 = (gb & 7) * 64;
    int c0 = (gb >> 3) * 64;
    float* As = smem;                // [16][64]
    float* Ws = smem + GKT * 64;     // [16][64]
    int tx = t & 15, ty = t >> 4;    // 16x16 threads, 4x4 each
    float acc[4][4] = {};

    for (int k0 = 0; k0 < D; k0 += GKT) {
        {
            int row = t >> 2, k = (t & 3) << 2;
            float4 v = *(const float4*)(g_h + (size_t)(r0 + row) * D + k0 + k);
            As[(k) * 64 + row] = v.x; As[(k + 1) * 64 + row] = v.y;
            As[(k + 2) * 64 + row] = v.z; As[(k + 3) * 64 + row] = v.w;
        }
        {
            int col = t >> 2, k = (t & 3) << 2;
            float4 v = *(const float4*)(g_Wbig + (size_t)(c0 + col) * KW + k0 + k);
            Ws[(k) * 64 + col] = v.x; Ws[(k + 1) * 64 + col] = v.y;
            Ws[(k + 2) * 64 + col] = v.z; Ws[(k + 3) * 64 + col] = v.w;
        }
        __syncthreads();
#pragma unroll
        for (int kk = 0; kk < GKT; kk++) {
            float a[4], w[4];
            *(float4*)a = *(const float4*)&As[kk * 64 + ty * 4];
            *(float4*)w = *(const float4*)&Ws[kk * 64 + tx * 4];
#pragma unroll
            for (int i = 0; i < 4; i++) {
#pragma unroll
                for (int j = 0; j < 4; j++) acc[i][j] += a[i] * w[j];
            }
        }
        __syncthreads();
    }
#pragma unroll
    for (int i = 0; i < 4; i++)
        *(float4*)(g_acc + (size_t)(r0 + ty * 4 + i) * GCOLS + c0 + tx * 4) = *(float4*)acc[i];
}

// ---------------- attention prologue / epilogue (8-lane-group scheme) -------------------
// warp layout: group g = lane>>3 owns one node/iter; sublane sl = lane&7 owns features
// [16sl, 16sl+16). Online softmax state per lane: m, s (group-wide), racc[16].

#define ATTN_PROLOGUE                                                              \
    int b = blockIdx.x;                                                            \
    int start = g_starts[b], end = g_starts[b + 1];                                \
    int warp = t >> 5;                                                             \
    int lane = t & 31;                                                             \
    int grp  = lane >> 3;                                                          \
    int sl   = lane & 7;                                                           \
    if (t < D) {                                                                   \
        float qv = g_h[(size_t)b * D + t];                                         \
        q_s[t] = qv * LOG2E;                 /* base-2 logits */                   \
        q_star[(size_t)b * KW + t] = qv;     /* q half */                          \
    }                                                                              \
    __syncthreads();                                                               \
    if (start >= end) {                      /* empty graph: r = 0 */              \
        if (t < D) q_star[(size_t)b * KW + D + t] = 0.f;                           \
        return;                                                                    \
    }                                                                              \
    const int stride = NWARP * GRP;                                                \
    int base0 = start + warp * GRP;                                                \
    int last  = end - 1;                                                           \
    int ngrp  = (base0 < end) ? (end - base0 + stride - 1) / stride : 0;

__device__ __forceinline__ void attn_epilogue_grp(int b, int t, int warp, int lane, int sl,
                                                  float m, float s, float* racc,
                                                  float* wm, float* wsum, float (*wr)[D],
                                                  float* q_star) {
    // combine 4 groups within the warp (features aligned across groups)
    float mw = fmaxf(m, __shfl_xor_sync(0xffffffffu, m, 8));
    mw = fmaxf(mw, __shfl_xor_sync(0xffffffffu, mw, 16));
    float cg = (m == -CUDART_INF_F) ? 0.f : ex2f(m - mw);
    float sw = s * cg;
    sw += __shfl_xor_sync(0xffffffffu, sw, 8);
    sw += __shfl_xor_sync(0xffffffffu, sw, 16);
#pragma unroll
    for (int k = 0; k < 16; k++) {
        float v = racc[k] * cg;
        v += __shfl_xor_sync(0xffffffffu, v, 8);
        v += __shfl_xor_sync(0xffffffffu, v, 16);
        racc[k] = v;
    }
    if (lane < 8) {
#pragma unroll
        for (int k = 0; k < 4; k++)
            *(float4*)&wr[warp][sl * 16 + 4 * k] = *(float4*)&racc[4 * k];
    }
    if (lane == 0) { wm[warp] = mw; wsum[warp] = sw; }
    __syncthreads();

    if (t < D) {
        float mb = wm[0];
#pragma unroll
        for (int w = 1; w < NWARP; w++) mb = fmaxf(mb, wm[w]);
        float stot = 0.f, rf = 0.f;
#pragma unroll
        for (int w = 0; w < NWARP; w++) {
            float c = ex2f(wm[w] - mb);   // 0 for warps that saw no node (wm=-inf)
            stot += c * wsum[w];
            rf   += c * wr[w][t];
        }
        q_star[(size_t)b * KW + D + t] = rf / (stot + 1e-16f);
    }
}

// online softmax update for one node's 16-feature slice (group-scope)
#define ATTN_UPDATE(XF)                                                            \
    {                                                                              \
        float dloc = 0.f;                                                          \
        _Pragma("unroll")                                                          \
        for (int c = 0; c < 4; c++) {                                              \
            float4 qv = *(const float4*)&q_s[sl * 16 + 4 * c];                     \
            dloc += XF[4*c] * qv.x + XF[4*c+1] * qv.y                              \
                  + XF[4*c+2] * qv.z + XF[4*c+3] * qv.w;                           \
        }                                                                          \
        dloc += __shfl_xor_sync(0xffffffffu, dloc, 1);                             \
        dloc += __shfl_xor_sync(0xffffffffu, dloc, 2);                             \
        dloc += __shfl_xor_sync(0xffffffffu, dloc, 4);                             \
        if (valid) {                                                               \
            if (dloc <= m) {                                                       \
                float w = ex2f(dloc - m);                                          \
                s += w;                                                            \
                _Pragma("unroll")                                                  \
                for (int k = 0; k < 16; k++) racc[k] += w * XF[k];                 \
            } else {                                                               \
                float sc = ex2f(m - dloc);   /* 0 when m=-inf */                   \
                m = dloc;                                                          \
                s = s * sc + 1.f;                                                  \
                _Pragma("unroll")                                                  \
                for (int k = 0; k < 16; k++) racc[k] = racc[k] * sc + XF[k];       \
            }                                                                      \
        }                                                                          \
    }

// ---------------- attention pass 0: f32 x, fp16 cache store -----------------------------
__global__ void __launch_bounds__(NTHR) attn_f32_kernel(const float* __restrict__ x,
                                                        float* __restrict__ q_star,
                                                        int do_store) {
    __shared__ __align__(16) float smem_buf[NWARP * STG * GRP * D];   // 48KB
    __shared__ __align__(16) float q_s[D];
    __shared__ float wm[NWARP], wsum[NWARP];
    __shared__ __align__(16) float wr[NWARP][D];

    int t = threadIdx.x;
    if (blockIdx.x >= BGR) { gruA_block(blockIdx.x - BGR, smem_buf, t); return; }

    float (*xs)[STG][GRP][D] = (float(*)[STG][GRP][D])smem_buf;
    ATTN_PROLOGUE

#pragma unroll
    for (int i = 0; i < STG; i++) {
        int gbase = base0 + i * stride;
        if (i < ngrp) {
#pragma unroll
            for (int j = 0; j < GRP; j++) {
                int node = min(gbase + j, last);
                cp16(&xs[warp][i][j][lane * 4], x + (size_t)node * D + lane * 4);
            }
        }
        cp_commit();
    }

    float m = -CUDART_INF_F, s = 0.f;
    float racc[16];
#pragma unroll
    for (int k = 0; k < 16; k++) racc[k] = 0.f;

    for (int gi = 0; gi < ngrp; gi++) {
        cp_wait<STG - 1>();
        __syncwarp();

        int slot = gi % STG;
        int node = base0 + gi * stride + grp;
        bool valid = node < end;

        float xf[16];
        {
            const float4* sp4 = (const float4*)(&xs[warp][slot][grp][sl * 16]);
#pragma unroll
            for (int c = 0; c < 4; c++) *(float4*)&xf[4 * c] = sp4[c];
        }
        if (do_store && valid) {                 // build fp16 x-cache
            uint4 u0, u1;
            __half2 h;
            h = __floats2half2_rn(xf[0], xf[1]);  u0.x = *(unsigned*)&h;
            h = __floats2half2_rn(xf[2], xf[3]);  u0.y = *(unsigned*)&h;
            h = __floats2half2_rn(xf[4], xf[5]);  u0.z = *(unsigned*)&h;
            h = __floats2half2_rn(xf[6], xf[7]);  u0.w = *(unsigned*)&h;
            h = __floats2half2_rn(xf[8], xf[9]);  u1.x = *(unsigned*)&h;
            h = __floats2half2_rn(xf[10], xf[11]); u1.y = *(unsigned*)&h;
            h = __floats2half2_rn(xf[12], xf[13]); u1.z = *(unsigned*)&h;
            h = __floats2half2_rn(xf[14], xf[15]); u1.w = *(unsigned*)&h;
            uint4* dst = (uint4*)&g_xh[(size_t)node * D + sl * 16];
            dst[0] = u0; dst[1] = u1;
        }

        ATTN_UPDATE(xf)
        __syncwarp();

        int nb = base0 + (gi + STG) * stride;
        if (gi + STG < ngrp) {
#pragma unroll
            for (int j = 0; j < GRP; j++) {
                int node2 = min(nb + j, last);
                cp16(&xs[warp][slot][j][lane * 4], x + (size_t)node2 * D + lane * 4);
            }
        }
        cp_commit();
    }

    attn_epilogue_grp(b, t, warp, lane, sl, m, s, racc, wm, wsum, wr, q_star);
}

// ---------------- attention passes 1-2: fp16 x-cache -----------------------------------
__global__ void __launch_bounds__(NTHR) attn_f16_kernel(float* __restrict__ q_star) {
    __shared__ __align__(16) float smem_buf[NWARP * STG * GRP * (D / 2)];  // 24KB halfs
    __shared__ __align__(16) float q_s[D];
    __shared__ float wm[NWARP], wsum[NWARP];
    __shared__ __align__(16) float wr[NWARP][D];

    int t = threadIdx.x;
    if (blockIdx.x >= BGR) { gruA_block(blockIdx.x - BGR, smem_buf, t); return; }

    __half (*xs)[STG][GRP][D] = (__half(*)[STG][GRP][D])smem_buf;
    ATTN_PROLOGUE

#pragma unroll
    for (int i = 0; i < STG; i++) {
        int gbase = base0 + i * stride;
        if (i < ngrp) {
#pragma unroll
            for (int j = 0; j < GRP; j++) {
                int node = min(gbase + j, last);
                cp8(&xs[warp][i][j][lane * 4], &g_xh[(size_t)node * D + lane * 4]);
            }
        }
        cp_commit();
    }

    float m = -CUDART_INF_F, s = 0.f;
    float racc[16];
#pragma unroll
    for (int k = 0; k < 16; k++) racc[k] = 0.f;

    for (int gi = 0; gi < ngrp; gi++) {
        cp_wait<STG - 1>();
        __syncwarp();

        int slot = gi % STG;
        int node = base0 + gi * stride + grp;
        bool valid = node < end;

        float xf[16];
        {
            const uint4* sp4 = (const uint4*)(&xs[warp][slot][grp][sl * 16]);
            uint4 u0 = sp4[0], u1 = sp4[1];
            float2 f;
            f = __half22float2(*(__half2*)&u0.x); xf[0] = f.x;  xf[1] = f.y;
            f = __half22float2(*(__half2*)&u0.y); xf[2] = f.x;  xf[3] = f.y;
            f = __half22float2(*(__half2*)&u0.z); xf[4] = f.x;  xf[5] = f.y;
            f = __half22float2(*(__half2*)&u0.w); xf[6] = f.x;  xf[7] = f.y;
            f = __half22float2(*(__half2*)&u1.x); xf[8] = f.x;  xf[9] = f.y;
            f = __half22float2(*(__half2*)&u1.y); xf[10] = f.x; xf[11] = f.y;
            f = __half22float2(*(__half2*)&u1.z); xf[12] = f.x; xf[13] = f.y;
            f = __half22float2(*(__half2*)&u1.w); xf[14] = f.x; xf[15] = f.y;
        }

        ATTN_UPDATE(xf)
        __syncwarp();

        int nb = base0 + (gi + STG) * stride;
        if (gi + STG < ngrp) {
#pragma unroll
            for (int j = 0; j < GRP; j++) {
                int node2 = min(nb + j, last);
                cp8(&xs[warp][slot][j][lane * 4], &g_xh[(size_t)node2 * D + lane * 4]);
            }
        }
        cp_commit();
    }

    attn_epilogue_grp(b, t, warp, lane, sl, m, s, racc, wm, wsum, wr, q_star);
}

// ---------------- launch ----------------
extern "C" void kernel_launch(void* const* d_in, const int* in_sizes, int n_in,
                              void* d_out, int out_size) {
    const float* x     = (const float*)d_in[0];
    const void*  batch = d_in[1];
    int base = (n_in >= 7) ? 3 : 2;    // d_in[2] may be the batch_size scalar
    const float* W_ih = (const float*)d_in[base];
    const float* W_hh = (const float*)d_in[base + 1];
    const float* b_ih = (const float*)d_in[base + 2];
    const float* b_hh = (const float*)d_in[base + 3];

    float* q_star = (float*)d_out;     // [BGR, 2D]
    int N = in_sizes[0] / D;
    int uh = (N <= MAXN) ? 1 : 0;      // fp16 cache fits?

    int init_blocks = PREP_BLKS + BIAS_BLKS + (N + 255) / 256;
    init_kernel<<<init_blocks, 256>>>(batch, N, W_ih, W_hh, b_ih, b_hh);

    dim3 bgrid(GCOLS / 64, BGR / 32);  // 128 blocks for grub
    const int AG = BGR + GRUA_BLKS;    // 576: attn + gruA

    // pass 1 (q = h1): f32 read + fp16 cache store; gruA(h1) embedded
    attn_f32_kernel<<<AG, NTHR>>>(x, q_star, uh);
    grub_kernel<<<bgrid, 128>>>(q_star);              // -> h2

    // pass 2 (q = h2): fp16 read; gruA(h2) embedded
    if (uh) attn_f16_kernel<<<AG, NTHR>>>(q_star);
    else    attn_f32_kernel<<<AG, NTHR>>>(x, q_star, 0);
    grub_kernel<<<bgrid, 128>>>(q_star);              // -> h3

    // pass 3 (q = h3): fp16 read; attn only
    if (uh) attn_f16_kernel<<<BGR, NTHR>>>(q_star);
    else    attn_f32_kernel<<<BGR, NTHR>>>(x, q_star, 0);
}

// round 16
// speedup vs baseline: 1.4944x; 1.4944x over previous
#include <cuda_runtime.h>
#include <math_constants.h>

#define D      128
#define BGR    512
#define NWARP  8
#define NTHR   256
#define KW     256          // GEMM K (= 2*D)
#define GCOLS  512          // GEMM output cols (4 gates x 128 features, interleaved)
#define STG    3            // per-warp cp.async ring depth
#define GRP    4            // nodes per stage
#define GRUA_BLKS 64        // embedded h-half GEMM blocks (64x64 tiles)
#define LOG2E  1.4426950408889634f

// init kernel block-range sizes
#define PREP_BLKS  512      // GCOLS*KW / 256
#define BIAS_BLKS  256      // BGR*D / 256

// ---------------- device scratch (no allocation allowed) ----------------
__device__ float g_h[BGR * D];            // hidden state (current)
__device__ float g_Wbig[GCOLS * KW];      // merged weights, col 4f+g
__device__ float g_bias[GCOLS];           // merged biases [br,bz,bin,bhn] per feature
__device__ int   g_starts[BGR + 1];       // segment boundaries (batch is sorted)
__device__ float g_acc[BGR * GCOLS];      // h-half GEMM partials (1MB)

__device__ __forceinline__ float sigf(float v) { return 1.f / (1.f + __expf(-v)); }
__device__ __forceinline__ float ex2f(float v) {
    float r; asm("ex2.approx.f32 %0, %1;" : "=f"(r) : "f"(v)); return r;
}

__device__ __forceinline__ void cp16(void* sdst, const void* gsrc) {
    unsigned s = (unsigned)__cvta_generic_to_shared(sdst);
    asm volatile("cp.async.cg.shared.global [%0], [%1], 16;" :: "r"(s), "l"(gsrc));
}
__device__ __forceinline__ void cp_commit() { asm volatile("cp.async.commit_group;"); }
template<int N> __device__ __forceinline__ void cp_wait() {
    asm volatile("cp.async.wait_group %0;" :: "n"(N));
}

// batch may be delivered as int32 or int64; sniff layout from a mid element.
__device__ __forceinline__ bool batch_is_i64(const void* bp, int N) {
    long long v = ((const long long*)bp)[N >> 2];
    return (v >= 0 && v < BGR);
}
__device__ __forceinline__ int batch_at(const void* bp, int i, bool is64) {
    int v = is64 ? (int)((const long long*)bp)[i] : ((const int*)bp)[i];
    return min(max(v, 0), BGR - 1);
}

// ---------------- fused init: prep (Wbig/bias) + step-1 h + segment starts -------------
__global__ void init_kernel(const void* __restrict__ batch, int N,
                            const float* __restrict__ W_ih, const float* __restrict__ W_hh,
                            const float* __restrict__ b_ih, const float* __restrict__ b_hh) {
    int bx = blockIdx.x;
    int t  = threadIdx.x;

    if (bx < PREP_BLKS) {
        int idx = bx * 256 + t;                 // < GCOLS*KW
        int c = idx >> 8;
        int k = idx & (KW - 1);
        int f = c >> 2, g = c & 3;
        float v;
        if (g == 0)      v = W_ih[(size_t)f * KW + k]         + (k < D ? W_hh[(size_t)f * D + k] : 0.f);
        else if (g == 1) v = W_ih[(size_t)(D + f) * KW + k]   + (k < D ? W_hh[(size_t)(D + f) * D + k] : 0.f);
        else if (g == 2) v = W_ih[(size_t)(2 * D + f) * KW + k];
        else             v = (k < D) ? W_hh[(size_t)(2 * D + f) * D + k] : 0.f;
        g_Wbig[(size_t)c * KW + k] = v;
        if (k == 0) {
            float b;
            if (g == 0)      b = b_ih[f] + b_hh[f];
            else if (g == 1) b = b_ih[D + f] + b_hh[D + f];
            else if (g == 2) b = b_ih[2 * D + f];
            else             b = b_hh[2 * D + f];
            g_bias[c] = b;
        }
    } else if (bx < PREP_BLKS + BIAS_BLKS) {
        int idx = (bx - PREP_BLKS) * 256 + t;   // < BGR*D
        int f = idx & (D - 1);
        float r = sigf(b_ih[f] + b_hh[f]);
        float z = sigf(b_ih[D + f] + b_hh[D + f]);
        float n = tanhf(b_ih[2 * D + f] + r * b_hh[2 * D + f]);
        g_h[idx] = (1.f - z) * n;
    } else {
        int i = (bx - PREP_BLKS - BIAS_BLKS) * 256 + t;
        if (i >= N) return;
        bool is64 = batch_is_i64(batch, N);
        int bi = batch_at(batch, i, is64);
        if (i == 0) {
            for (int b = 0; b <= bi; b++) g_starts[b] = 0;
        } else {
            int bp = batch_at(batch, i - 1, is64);
            for (int b = bp + 1; b <= bi; b++) g_starts[b] = i;
        }
        if (i == N - 1) {
            for (int b = bi + 1; b <= BGR; b++) g_starts[b] = N;
        }
    }
}

// ---------------- gruB: r-half GEMM + gate epilogue (critical path) --------------------
#define GKT 16
__global__ void __launch_bounds__(128) grub_kernel(const float* __restrict__ q_star) {
    __shared__ __align__(16) float As[GKT][32];
    __shared__ __align__(16) float Ws[GKT][64];

    int t  = threadIdx.x;
    int tx = t & 15;
    int ty = t >> 4;           // 0..7 -> 4 rows each
    int r0 = blockIdx.y * 32;
    int c0 = blockIdx.x * 64;

    float acc[4][4];
#pragma unroll
    for (int i = 0; i < 4; i++)
        *(float4*)acc[i] = *(const float4*)(g_acc + (size_t)(r0 + ty * 4 + i) * GCOLS + c0 + tx * 4);

    for (int k0 = 0; k0 < D; k0 += GKT) {
        {   // A tile 32r x 16k from q_star r-half
            int row = t >> 2, k = (t & 3) << 2;
            float4 v = *(const float4*)(q_star + (size_t)(r0 + row) * KW + D + k0 + k);
            As[k][row] = v.x; As[k + 1][row] = v.y; As[k + 2][row] = v.z; As[k + 3][row] = v.w;
        }
        {   // W tile 64c x 16k from Wbig k in [128,256)
            int col = t >> 1, k = (t & 1) << 3;
            const float* wp = g_Wbig + (size_t)(c0 + col) * KW + D + k0 + k;
            float4 v0 = *(const float4*)wp;
            float4 v1 = *(const float4*)(wp + 4);
            Ws[k][col]     = v0.x; Ws[k + 1][col] = v0.y; Ws[k + 2][col] = v0.z; Ws[k + 3][col] = v0.w;
            Ws[k + 4][col] = v1.x; Ws[k + 5][col] = v1.y; Ws[k + 6][col] = v1.z; Ws[k + 7][col] = v1.w;
        }
        __syncthreads();
#pragma unroll
        for (int kk = 0; kk < GKT; kk++) {
            float a[4], w[4];
            *(float4*)a = *(const float4*)&As[kk][ty * 4];
            *(float4*)w = *(const float4*)&Ws[kk][tx * 4];
#pragma unroll
            for (int i = 0; i < 4; i++) {
#pragma unroll
                for (int j = 0; j < 4; j++) acc[i][j] += a[i] * w[j];
            }
        }
        __syncthreads();
    }

    int f = (c0 >> 2) + tx;
    float4 gb = *(const float4*)&g_bias[4 * f];   // [br, bz, bin, bhn]
#pragma unroll
    for (int i = 0; i < 4; i++) {
        int row = r0 + ty * 4 + i;
        float hold = q_star[(size_t)row * KW + f];    // h_old = q half of q_star
        float r = sigf(acc[i][0] + gb.x);
        float z = sigf(acc[i][1] + gb.y);
        float n = tanhf(acc[i][2] + gb.z + r * (acc[i][3] + gb.w));
        g_h[(size_t)row * D + f] = (1.f - z) * n + z * hold;
    }
}

// ---------------- attention (per-warp cp.async ring) + embedded h-half GEMM ------------
__global__ void __launch_bounds__(NTHR) attn_kernel(const float* __restrict__ x,
                                                    float* __restrict__ q_star) {
    __shared__ __align__(16) float xs[NWARP][STG][GRP][D];   // 48KB (aliased by gruA)
    __shared__ __align__(16) float q_s[D];
    __shared__ float wm[NWARP], wsum[NWARP];
    __shared__ __align__(16) float wr[NWARP][D];

    int t = threadIdx.x;

    if (blockIdx.x >= BGR) {
        // ---------- gruA: g_acc = h @ Wbig[:, :128]^T (64x64 tile) ----------
        int gb = blockIdx.x - BGR;
        int r0 = (gb & 7) * 64;
        int c0 = (gb >> 3) * 64;
        float* As = (float*)xs;          // [16][64]
        float* Ws = As + GKT * 64;       // [16][64]
        int tx = t & 15, ty = t >> 4;    // 16x16 threads, 4x4 each
        float acc[4][4] = {};

        for (int k0 = 0; k0 < D; k0 += GKT) {
            {
                int row = t >> 2, k = (t & 3) << 2;
                float4 v = *(const float4*)(g_h + (size_t)(r0 + row) * D + k0 + k);
                As[(k) * 64 + row]     = v.x;
                As[(k + 1) * 64 + row] = v.y;
                As[(k + 2) * 64 + row] = v.z;
                As[(k + 3) * 64 + row] = v.w;
            }
            {
                int col = t >> 2, k = (t & 3) << 2;
                float4 v = *(const float4*)(g_Wbig + (size_t)(c0 + col) * KW + k0 + k);
                Ws[(k) * 64 + col]     = v.x;
                Ws[(k + 1) * 64 + col] = v.y;
                Ws[(k + 2) * 64 + col] = v.z;
                Ws[(k + 3) * 64 + col] = v.w;
            }
            __syncthreads();
#pragma unroll
            for (int kk = 0; kk < GKT; kk++) {
                float a[4], w[4];
                *(float4*)a = *(const float4*)&As[kk * 64 + ty * 4];
                *(float4*)w = *(const float4*)&Ws[kk * 64 + tx * 4];
#pragma unroll
                for (int i = 0; i < 4; i++) {
#pragma unroll
                    for (int j = 0; j < 4; j++) acc[i][j] += a[i] * w[j];
                }
            }
            __syncthreads();
        }
#pragma unroll
        for (int i = 0; i < 4; i++)
            *(float4*)(g_acc + (size_t)(r0 + ty * 4 + i) * GCOLS + c0 + tx * 4) = *(float4*)acc[i];
        return;
    }

    // ---------- attention ----------
    int b = blockIdx.x;
    int start = g_starts[b];
    int end   = g_starts[b + 1];
    int warp = t >> 5;
    int lane = t & 31;

    if (t < D) {
        float qv = g_h[(size_t)b * D + t];
        q_s[t] = qv * LOG2E;                 // base-2 logits
        q_star[(size_t)b * (2 * D) + t] = qv;   // q half (always)
    }
    __syncthreads();

    if (start >= end) {                 // empty graph: r = 0
        if (t < D) q_star[(size_t)b * (2 * D) + D + t] = 0.f;
        return;
    }

    const int stride = NWARP * GRP;     // 32
    int base0 = start + warp * GRP;
    int last  = end - 1;
    int ngrp  = (base0 < end) ? (end - base0 + stride - 1) / stride : 0;

#pragma unroll
    for (int i = 0; i < STG; i++) {
        int gbase = base0 + i * stride;
        if (i < ngrp) {
#pragma unroll
            for (int j = 0; j < GRP; j++) {
                int node = min(gbase + j, last);
                cp16(&xs[warp][i][j][lane * 4], x + (size_t)node * D + lane * 4);
            }
        }
        cp_commit();
    }

    float4 qf = *(const float4*)(q_s + lane * 4);
    float m = -CUDART_INF_F;
    float s = 0.f;
    float4 racc = make_float4(0.f, 0.f, 0.f, 0.f);

    for (int gi = 0; gi < ngrp; gi++) {
        cp_wait<STG - 1>();             // group gi resident (per-thread state)
        __syncwarp();                   // cross-lane smem visibility within warp

        int slot = gi % STG;
        int gbase = base0 + gi * stride;
        float4 xv[GRP];
        float  d[GRP];
#pragma unroll
        for (int j = 0; j < GRP; j++) {
            xv[j] = *(const float4*)&xs[warp][slot][j][lane * 4];
            d[j] = xv[j].x * qf.x + xv[j].y * qf.y + xv[j].z * qf.z + xv[j].w * qf.w;
        }
#pragma unroll
        for (int off = 16; off >= 1; off >>= 1) {
#pragma unroll
            for (int j = 0; j < GRP; j++) d[j] += __shfl_xor_sync(0xffffffffu, d[j], off);
        }
#pragma unroll
        for (int j = 0; j < GRP; j++) {
            if (gbase + j >= end) break;           // warp-uniform; pads never touch m
            if (d[j] <= m) {
                float w = ex2f(d[j] - m);
                s += w;
                racc.x += w * xv[j].x; racc.y += w * xv[j].y;
                racc.z += w * xv[j].z; racc.w += w * xv[j].w;
            } else {                               // new max (always on warp's first node)
                float sc = ex2f(m - d[j]);         // 0 when m=-inf
                m = d[j];
                s = s * sc + 1.f;
                racc.x = racc.x * sc + xv[j].x; racc.y = racc.y * sc + xv[j].y;
                racc.z = racc.z * sc + xv[j].z; racc.w = racc.w * sc + xv[j].w;
            }
        }
        __syncwarp();                   // all lanes done reading slot before refill

        int nb = base0 + (gi + STG) * stride;      // refill slot with group gi+STG
        if (gi + STG < ngrp) {
#pragma unroll
            for (int j = 0; j < GRP; j++) {
                int node = min(nb + j, last);
                cp16(&xs[warp][slot][j][lane * 4], x + (size_t)node * D + lane * 4);
            }
        }
        cp_commit();
    }

    if (lane == 0) { wm[warp] = m; wsum[warp] = s; }
    *(float4*)(&wr[warp][lane * 4]) = racc;
    __syncthreads();

    if (t < D) {
        float mb = wm[0];
#pragma unroll
        for (int w = 1; w < NWARP; w++) mb = fmaxf(mb, wm[w]);
        float stot = 0.f, rf = 0.f;
#pragma unroll
        for (int w = 0; w < NWARP; w++) {
            float c = ex2f(wm[w] - mb);   // 0 for warps that saw no node (wm=-inf)
            stot += c * wsum[w];
            rf   += c * wr[w][t];
        }
        q_star[(size_t)b * (2 * D) + D + t] = rf / (stot + 1e-16f);
    }
}

// ---------------- launch ----------------
extern "C" void kernel_launch(void* const* d_in, const int* in_sizes, int n_in,
                              void* d_out, int out_size) {
    const float* x     = (const float*)d_in[0];
    const void*  batch = d_in[1];
    int base = (n_in >= 7) ? 3 : 2;    // d_in[2] may be the batch_size scalar
    const float* W_ih = (const float*)d_in[base];
    const float* W_hh = (const float*)d_in[base + 1];
    const float* b_ih = (const float*)d_in[base + 2];
    const float* b_hh = (const float*)d_in[base + 3];

    float* q_star = (float*)d_out;     // [BGR, 2D]
    int N = in_sizes[0] / D;

    int init_blocks = PREP_BLKS + BIAS_BLKS + (N + 255) / 256;
    init_kernel<<<init_blocks, 256>>>(batch, N, W_ih, W_hh, b_ih, b_hh);

    dim3 bgrid(GCOLS / 64, BGR / 32);  // 128 blocks for grub

    // pass k: attention (blocks 0..511) + h-half GEMM for step k+1 (blocks 512..575)
    attn_kernel<<<BGR + GRUA_BLKS, NTHR>>>(x, q_star);
    grub_kernel<<<bgrid, 128>>>(q_star);

    attn_kernel<<<BGR + GRUA_BLKS, NTHR>>>(x, q_star);
    grub_kernel<<<bgrid, 128>>>(q_star);

    attn_kernel<<<BGR, NTHR>>>(x, q_star);
}